// round 13
// baseline (speedup 1.0000x reference)
#include <cuda_runtime.h>
#include <cuda_bf16.h>
#include <cuda_fp16.h>
#include <math.h>
#include <stdint.h>

#define D_MODEL 1024
#define N_HEADS 16
#define HEAD_DIM 64
#define BATCH 4
#define SEQ 2048
#define M_ROWS (BATCH * SEQ)          // 8192
#define QKV_N (3 * D_MODEL)           // 3072

// ======================= scratch (static device globals) =======================
__device__ __align__(16) float g_cos[SEQ * 32];
__device__ __align__(16) float g_sin[SEQ * 32];
__device__ __align__(16) __half g_xf[M_ROWS * D_MODEL];
__device__ __align__(16) __half g_wqf[D_MODEL * QKV_N];       // transposed [3072][1024]
__device__ __align__(16) __half g_aof[M_ROWS * D_MODEL];
__device__ __align__(16) __half g_wof[D_MODEL * D_MODEL];     // transposed [1024][1024]
__device__ __align__(16) __nv_bfloat16 g_qh[BATCH * N_HEADS * SEQ * HEAD_DIM];
__device__ __align__(16) __nv_bfloat16 g_ql[BATCH * N_HEADS * SEQ * HEAD_DIM];
__device__ __align__(16) __nv_bfloat16 g_kh[BATCH * N_HEADS * SEQ * HEAD_DIM];
__device__ __align__(16) __nv_bfloat16 g_kl[BATCH * N_HEADS * SEQ * HEAD_DIM];
__device__ __align__(16) __half g_vf[BATCH * N_HEADS * SEQ * HEAD_DIM];

// ======================= PTX helpers =======================
__device__ __forceinline__ uint32_t smem_to_u32(const void* smem_ptr) {
    uint32_t addr;
    asm("{ .reg .u64 tmp; cvta.to.shared.u64 tmp, %1; cvt.u32.u64 %0, tmp; }"
        : "=r"(addr) : "l"(smem_ptr));
    return addr;
}
__device__ __forceinline__ void cpa16(uint32_t s, const void* g) {
    asm volatile("cp.async.cg.shared.global [%0], [%1], 16;" :: "r"(s), "l"(g));
}
__device__ __forceinline__ void cpa_commit() {
    asm volatile("cp.async.commit_group;" ::: "memory");
}
__device__ __forceinline__ void ldsm4(uint32_t* r, uint32_t addr) {
    asm volatile("ldmatrix.sync.aligned.m8n8.x4.shared.b16 {%0,%1,%2,%3}, [%4];"
        : "=r"(r[0]), "=r"(r[1]), "=r"(r[2]), "=r"(r[3]) : "r"(addr));
}
__device__ __forceinline__ void ldsm4t(uint32_t* r, uint32_t addr) {
    asm volatile("ldmatrix.sync.aligned.m8n8.x4.trans.shared.b16 {%0,%1,%2,%3}, [%4];"
        : "=r"(r[0]), "=r"(r[1]), "=r"(r[2]), "=r"(r[3]) : "r"(addr));
}
__device__ __forceinline__ void mma16816(float* c, const uint32_t* a, uint32_t b0, uint32_t b1) {
    asm("mma.sync.aligned.m16n8k16.row.col.f32.bf16.bf16.f32 "
        "{%0,%1,%2,%3}, {%4,%5,%6,%7}, {%8,%9}, {%0,%1,%2,%3};"
        : "+f"(c[0]), "+f"(c[1]), "+f"(c[2]), "+f"(c[3])
        : "r"(a[0]), "r"(a[1]), "r"(a[2]), "r"(a[3]), "r"(b0), "r"(b1));
}
__device__ __forceinline__ void mmah(float* c, const uint32_t* a, uint32_t b0, uint32_t b1) {
    asm("mma.sync.aligned.m16n8k16.row.col.f32.f16.f16.f32 "
        "{%0,%1,%2,%3}, {%4,%5,%6,%7}, {%8,%9}, {%0,%1,%2,%3};"
        : "+f"(c[0]), "+f"(c[1]), "+f"(c[2]), "+f"(c[3])
        : "r"(a[0]), "r"(a[1]), "r"(a[2]), "r"(a[3]), "r"(b0), "r"(b1));
}
__device__ __forceinline__ uint32_t pack_h2(float a, float b) {
    __half2 h = __floats2half2_rn(a, b);
    return *(uint32_t*)&h;
}
__device__ __forceinline__ uint32_t pack_bf2(float a, float b) {
    __nv_bfloat162 h = __floats2bfloat162_rn(a, b);
    return *(uint32_t*)&h;
}
__device__ __forceinline__ float ex2f(float x) {
    float r;
    asm("ex2.approx.ftz.f32 %0, %1;" : "=f"(r) : "f"(x));
    return r;
}

// ======================= RoPE table (fp32) =======================
__global__ void rope_table_kernel() {
    int idx = blockIdx.x * blockDim.x + threadIdx.x;   // 0..65535
    int t = idx >> 5;
    int i = idx & 31;
    float inv = exp2f(-(float)(2 * i) * (1.0f / 64.0f) * 13.28771237954945f); // log2(10000)
    float a = (float)t * inv;
    float s, c;
    sincosf(a, &s, &c);
    g_cos[t * 32 + i] = c;
    g_sin[t * 32 + i] = s;
}

// ======================= fp32 -> fp16 =======================
__global__ void conv_f16_kernel(const float* __restrict__ in,
                                __half* __restrict__ out, int n) {
    int i = blockIdx.x * blockDim.x + threadIdx.x;
    int stride = gridDim.x * blockDim.x;
    for (; i < n; i += stride) out[i] = __float2half_rn(in[i]);
}

// ======================= transpose fp32 -> fp16 =======================
__global__ void trans_f16_kernel(const float* __restrict__ W,
                                 __half* __restrict__ T, int K, int N) {
    __shared__ float t[32][33];
    int n = blockIdx.x * 32 + threadIdx.x;
    int k0 = blockIdx.y * 32;
#pragma unroll
    for (int r = 0; r < 32; r += 8)
        t[threadIdx.y + r][threadIdx.x] = W[(size_t)(k0 + threadIdx.y + r) * N + n];
    __syncthreads();
    int k = k0 + threadIdx.x;
#pragma unroll
    for (int r = 0; r < 32; r += 8) {
        int n2 = blockIdx.x * 32 + threadIdx.y + r;
        T[(size_t)n2 * K + k] = __float2half_rn(t[threadIdx.x][threadIdx.y + r]);
    }
}

// ======================= fp16 warp-MMA GEMM, K-stage 64, 4 warps (2x2) ==============
// rows padded to 144B (128B data + 16 pad) -> conflict-free ldmatrix
#define GTILE 18432                     // 128 rows * 144B
#define GSTG  (2 * GTILE)               // A + B per stage
#define GEMM_SMEM (2 * GSTG)            // 73728 (double buffered)

__device__ __forceinline__ void load_stage(
    uint32_t sb, const __half* __restrict__ Ah, const __half* __restrict__ Bh,
    int m0, int n0, int k0, int tid)
{
    const __half* gp[2] = { Ah, Bh };
    int rb[2] = { m0, n0 };
#pragma unroll
    for (int i = 0; i < 16; i++) {
        int ch = tid + i * 128;              // 0..2047
        int tlb = ch >> 10;
        int w2 = ch & 1023;
        int row = w2 >> 3, c16 = w2 & 7;
        cpa16(sb + tlb * GTILE + row * 144 + c16 * 16,
              gp[tlb] + (size_t)(rb[tlb] + row) * 1024 + k0 + c16 * 8);
    }
}

template <int EPI>  // 0: RoPE+split scatter to qh/ql/kh/kl + fp16 V, 1: plain fp32 store
__global__ void __launch_bounds__(128, 2) gemm_mma_kernel(
    const __half* __restrict__ Ah, const __half* __restrict__ Bh,
    float* __restrict__ Cout)
{
    extern __shared__ char dsm[];
    uint32_t sb0 = smem_to_u32(dsm);
    int tid = threadIdx.x, lane = tid & 31, wid = tid >> 5;
    int warpM = wid >> 1, warpN = wid & 1;      // 2 x 2
    int m0 = blockIdx.y * 128, n0 = blockIdx.x * 128;

    float c[4][8][4];
#pragma unroll
    for (int i = 0; i < 4; i++)
#pragma unroll
        for (int j = 0; j < 8; j++)
#pragma unroll
            for (int k = 0; k < 4; k++) c[i][j][k] = 0.f;

    uint32_t aRow = (uint32_t)((warpM * 64 + (lane & 15)) * 144 + ((lane >> 4) << 4));
    uint32_t bRow = (uint32_t)((warpN * 64 + ((lane >> 4) << 3) + (lane & 7)) * 144 +
                               (((lane >> 3) & 1) << 4));

    const int NS = 16;
    load_stage(sb0, Ah, Bh, m0, n0, 0, tid);
    cpa_commit();

    for (int s = 0; s < NS; s++) {
        uint32_t sb = sb0 + (uint32_t)((s & 1) * GSTG);
        if (s + 1 < NS) {
            load_stage(sb0 + (uint32_t)(((s + 1) & 1) * GSTG),
                       Ah, Bh, m0, n0, (s + 1) * 64, tid);
            cpa_commit();
            asm volatile("cp.async.wait_group 1;" ::: "memory");
        } else {
            asm volatile("cp.async.wait_group 0;" ::: "memory");
        }
        __syncthreads();

#pragma unroll
        for (int k16 = 0; k16 < 4; k16++) {
            uint32_t koff = (uint32_t)(k16 * 32);
            uint32_t af[4][4], bf[4][4];
#pragma unroll
            for (int mf = 0; mf < 4; mf++)
                ldsm4(af[mf], sb + aRow + (uint32_t)(mf * 2304) + koff);
#pragma unroll
            for (int nf2 = 0; nf2 < 4; nf2++)
                ldsm4(bf[nf2], sb + GTILE + bRow + (uint32_t)(nf2 * 2304) + koff);
#pragma unroll
            for (int mf = 0; mf < 4; mf++)
#pragma unroll
                for (int nf = 0; nf < 8; nf++)
                    mmah(c[mf][nf], af[mf],
                         bf[nf >> 1][(nf & 1) * 2], bf[nf >> 1][(nf & 1) * 2 + 1]);
        }
        __syncthreads();
    }

    // ---------------- epilogue ----------------
    int mBase = m0 + warpM * 64 + (lane >> 2);
    if (EPI == 1) {
        int nBase = n0 + warpN * 64 + (lane & 3) * 2;
#pragma unroll
        for (int mf = 0; mf < 4; mf++)
#pragma unroll
            for (int nf = 0; nf < 8; nf++) {
                int row = mBase + mf * 16;
                int col = nBase + nf * 8;
                *(float2*)(Cout + (size_t)row * 1024 + col) =
                    make_float2(c[mf][nf][0], c[mf][nf][1]);
                *(float2*)(Cout + (size_t)(row + 8) * 1024 + col) =
                    make_float2(c[mf][nf][2], c[mf][nf][3]);
            }
        return;
    }

    // EPI==0: this warp's 64-col span = exactly one (sel, head)
    int col0 = n0 + warpN * 64;
    int sel = col0 >> 10;                 // 0:Q 1:K 2:V
    int h = (col0 >> 6) & 15;
    int lc = (lane & 3) * 2;

    if (sel == 2) {
#pragma unroll
        for (int mf = 0; mf < 4; mf++) {
            int row = mBase + mf * 16;
            int b = row >> 11, t = row & 2047;
            size_t base = ((size_t)((b * 16 + h) * 2048)) * 64;
#pragma unroll
            for (int nf = 0; nf < 8; nf++) {
                int d = lc + nf * 8;
                *(uint32_t*)(g_vf + base + (size_t)t * 64 + d) =
                    pack_h2(c[mf][nf][0], c[mf][nf][1]);
                *(uint32_t*)(g_vf + base + (size_t)(t + 8) * 64 + d) =
                    pack_h2(c[mf][nf][2], c[mf][nf][3]);
            }
        }
    } else {
        const float SCQ = 0.125f * 1.44269504088896f;
        float scale = (sel == 0) ? SCQ : 1.f;
        __nv_bfloat16* Gh = (sel == 0) ? g_qh : g_kh;
        __nv_bfloat16* Gl = (sel == 0) ? g_ql : g_kl;
#pragma unroll
        for (int mf = 0; mf < 4; mf++) {
            int row = mBase + mf * 16;
            int b = row >> 11, t = row & 2047;
            size_t base = ((size_t)((b * 16 + h) * 2048)) * 64;
#pragma unroll
            for (int nfp = 0; nfp < 4; nfp++) {
                int i0 = lc + nfp * 8;
                float2 cs0 = *(const float2*)&g_cos[t * 32 + i0];
                float2 sn0 = *(const float2*)&g_sin[t * 32 + i0];
                float2 cs8 = *(const float2*)&g_cos[(t + 8) * 32 + i0];
                float2 sn8 = *(const float2*)&g_sin[(t + 8) * 32 + i0];
#pragma unroll
                for (int rr = 0; rr < 2; rr++) {
                    float cx = rr ? cs8.x : cs0.x, cy = rr ? cs8.y : cs0.y;
                    float sx = rr ? sn8.x : sn0.x, sy = rr ? sn8.y : sn0.y;
                    float x1a = c[mf][nfp][rr * 2],     x1b = c[mf][nfp][rr * 2 + 1];
                    float x2a = c[mf][nfp + 4][rr * 2], x2b = c[mf][nfp + 4][rr * 2 + 1];
                    float r1a = (x1a * cx - x2a * sx) * scale;
                    float r1b = (x1b * cy - x2b * sy) * scale;
                    float r2a = (x2a * cx + x1a * sx) * scale;
                    float r2b = (x2b * cy + x1b * sy) * scale;
                    __nv_bfloat16 h1a = __float2bfloat16(r1a), h1b = __float2bfloat16(r1b);
                    __nv_bfloat16 h2a = __float2bfloat16(r2a), h2b = __float2bfloat16(r2b);
                    size_t off = base + (size_t)(t + rr * 8) * 64 + i0;
                    *(uint32_t*)(Gh + off) =
                        ((uint32_t)*(uint16_t*)&h1a) | (((uint32_t)*(uint16_t*)&h1b) << 16);
                    *(uint32_t*)(Gh + off + 32) =
                        ((uint32_t)*(uint16_t*)&h2a) | (((uint32_t)*(uint16_t*)&h2b) << 16);
                    *(uint32_t*)(Gl + off) =
                        pack_bf2(r1a - __bfloat162float(h1a), r1b - __bfloat162float(h1b));
                    *(uint32_t*)(Gl + off + 32) =
                        pack_bf2(r2a - __bfloat162float(h2a), r2b - __bfloat162float(h2b));
                }
            }
        }
    }
}

// ======================= Tensor-core flash: 4 warps x 32 q-rows =======================
// S = QK^T : 3-term bf16.  O = PV : 2-term fp16 (P split hi/lo, V single).
#define FRS 144
#define FTILE (64 * FRS)                 // 9216
#define FQ_B  (128 * FRS)                // 18432
#define FSB_Q 0
#define FSB_KV (2 * FQ_B)                // 36864
#define FSTG_B (3 * FTILE)               // Khi, Klo, Vf = 27648
#define FLASH_SMEM (FSB_KV + 2 * FSTG_B) // 92160

__device__ __forceinline__ void flash_load_q(uint32_t sb, int bh, int q0, int tid) {
#pragma unroll
    for (int i = 0; i < 16; i++) {
        int ch = tid + i * 128;               // 0..2047
        int tl = ch >> 10;
        int r = (ch >> 3) & 127, c16 = ch & 7;
        const __nv_bfloat16* src = (tl ? g_ql : g_qh) +
            ((size_t)bh * SEQ + q0 + r) * 64 + c16 * 8;
        cpa16(sb + FSB_Q + tl * FQ_B + r * FRS + c16 * 16, src);
    }
}
__device__ __forceinline__ void flash_load_kv(uint32_t sb, int bh, int kbase, int stg, int tid) {
    uint32_t d0 = sb + FSB_KV + stg * FSTG_B;
#pragma unroll
    for (int i = 0; i < 12; i++) {
        int ch = tid + i * 128;               // 0..1535
        int tl = ch >> 9;                     // 0 Khi, 1 Klo, 2 Vf
        int r = (ch >> 3) & 63, c16 = ch & 7;
        const void* src;
        if (tl == 0)      src = g_kh + ((size_t)bh * SEQ + kbase + r) * 64 + c16 * 8;
        else if (tl == 1) src = g_kl + ((size_t)bh * SEQ + kbase + r) * 64 + c16 * 8;
        else              src = g_vf + ((size_t)bh * SEQ + kbase + r) * 64 + c16 * 8;
        cpa16(d0 + tl * FTILE + r * FRS + c16 * 16, src);
    }
}

__global__ void __launch_bounds__(128, 2) flash_tc_kernel() {
    extern __shared__ char dsm[];
    uint32_t sb = smem_to_u32(dsm);
    int tid = threadIdx.x, lane = tid & 31, w = tid >> 5;
    int qt = 15 - (int)blockIdx.x;
    int bh = blockIdx.y;
    int q0 = qt * 128;
    int nkt = qt * 2 + 2;

    flash_load_q(sb, bh, q0, tid);
    flash_load_kv(sb, bh, 0, 0, tid);
    cpa_commit();

    uint32_t aQh[2][4][4], aQl[2][4][4];
    float o[2][8][4];
#pragma unroll
    for (int mf = 0; mf < 2; mf++)
#pragma unroll
        for (int i = 0; i < 8; i++)
#pragma unroll
            for (int j = 0; j < 4; j++) o[mf][i][j] = 0.f;
    float ls[2][2] = {{0.f, 0.f}, {0.f, 0.f}};

    uint32_t qAddr = (uint32_t)((w * 32 + (lane & 15)) * FRS + ((lane >> 4) << 4));
    uint32_t kLane = (uint32_t)((((lane >> 4) << 3) + (lane & 7)) * FRS + (((lane >> 3) & 1) << 4));
    uint32_t vLane = (uint32_t)(((lane & 7) + ((lane >> 3) & 1) * 8) * FRS + ((lane >> 4) << 4));

    for (int kt = 0; kt < nkt; kt++) {
        if (kt + 1 < nkt) {
            flash_load_kv(sb, bh, (kt + 1) * 64, (kt + 1) & 1, tid);
            cpa_commit();
            asm volatile("cp.async.wait_group 1;" ::: "memory");
        } else {
            asm volatile("cp.async.wait_group 0;" ::: "memory");
        }
        __syncthreads();

        if (kt == 0) {
#pragma unroll
            for (int mf = 0; mf < 2; mf++)
#pragma unroll
                for (int kk = 0; kk < 4; kk++) {
                    uint32_t a = sb + FSB_Q + qAddr + (uint32_t)(mf * 16 * FRS) + kk * 32;
                    ldsm4(aQh[mf][kk], a);
                    ldsm4(aQl[mf][kk], a + FQ_B);
                }
        }

        uint32_t stg = sb + FSB_KV + (kt & 1) * FSTG_B;
        int kbase = kt * 64;

        // ---- S = Q K^T (3-term bf16, term-major per kk) ----
        float c[2][8][4];
#pragma unroll
        for (int mf = 0; mf < 2; mf++)
#pragma unroll
            for (int i = 0; i < 8; i++)
#pragma unroll
                for (int j = 0; j < 4; j++) c[mf][i][j] = 0.f;

#pragma unroll
        for (int kk = 0; kk < 4; kk++) {
            uint32_t bKh[4][4], bKl[4][4];
#pragma unroll
            for (int nf2 = 0; nf2 < 4; nf2++) {
                uint32_t ba = stg + (uint32_t)(nf2 * 16 * FRS) + kLane + kk * 32;
                ldsm4(bKh[nf2], ba);
                ldsm4(bKl[nf2], ba + FTILE);
            }
#pragma unroll
            for (int mf = 0; mf < 2; mf++)
#pragma unroll
                for (int nf = 0; nf < 8; nf++)
                    mma16816(c[mf][nf], aQh[mf][kk],
                             bKh[nf >> 1][(nf & 1) * 2], bKh[nf >> 1][(nf & 1) * 2 + 1]);
#pragma unroll
            for (int mf = 0; mf < 2; mf++)
#pragma unroll
                for (int nf = 0; nf < 8; nf++)
                    mma16816(c[mf][nf], aQh[mf][kk],
                             bKl[nf >> 1][(nf & 1) * 2], bKl[nf >> 1][(nf & 1) * 2 + 1]);
#pragma unroll
            for (int mf = 0; mf < 2; mf++)
#pragma unroll
                for (int nf = 0; nf < 8; nf++)
                    mma16816(c[mf][nf], aQl[mf][kk],
                             bKh[nf >> 1][(nf & 1) * 2], bKh[nf >> 1][(nf & 1) * 2 + 1]);
        }

        // ---- mask + exp + pack P (fp16 hi/lo) ----
        bool needmask = (kbase + 63) > (q0 + w * 32);
        uint32_t aPh[2][4][4], aPl[2][4][4];
#pragma unroll
        for (int mf = 0; mf < 2; mf++) {
            int qrA = q0 + w * 32 + mf * 16 + (lane >> 2);
#pragma unroll
            for (int nf = 0; nf < 8; nf++) {
                if (needmask) {
                    int key0 = kbase + nf * 8 + (lane & 3) * 2;
                    if (key0 > qrA)         c[mf][nf][0] = -100000.f;
                    if (key0 + 1 > qrA)     c[mf][nf][1] = -100000.f;
                    if (key0 > qrA + 8)     c[mf][nf][2] = -100000.f;
                    if (key0 + 1 > qrA + 8) c[mf][nf][3] = -100000.f;
                }
                float p0 = ex2f(c[mf][nf][0]), p1 = ex2f(c[mf][nf][1]);
                float p2 = ex2f(c[mf][nf][2]), p3 = ex2f(c[mf][nf][3]);
                ls[mf][0] += p0 + p1;
                ls[mf][1] += p2 + p3;
                __half h0 = __float2half_rn(p0), h1 = __float2half_rn(p1);
                __half h2 = __float2half_rn(p2), h3 = __float2half_rn(p3);
                int kk = nf >> 1, sl = (nf & 1) * 2;
                aPh[mf][kk][sl]     = ((uint32_t)*(uint16_t*)&h0) | (((uint32_t)*(uint16_t*)&h1) << 16);
                aPh[mf][kk][sl + 1] = ((uint32_t)*(uint16_t*)&h2) | (((uint32_t)*(uint16_t*)&h3) << 16);
                aPl[mf][kk][sl]     = pack_h2(p0 - __half2float(h0), p1 - __half2float(h1));
                aPl[mf][kk][sl + 1] = pack_h2(p2 - __half2float(h2), p3 - __half2float(h3));
            }
        }

        // ---- O += P V (2-term fp16, term-major per kk) ----
        uint32_t vstg = stg + 2 * FTILE;
#pragma unroll
        for (int kk = 0; kk < 4; kk++) {
            uint32_t vf[4][4];
#pragma unroll
            for (int df2 = 0; df2 < 4; df2++)
                ldsm4t(vf[df2], vstg + (uint32_t)(kk * 16 * FRS) + vLane + df2 * 32);
#pragma unroll
            for (int mf = 0; mf < 2; mf++)
#pragma unroll
                for (int nf = 0; nf < 8; nf++)
                    mmah(o[mf][nf], aPh[mf][kk],
                         vf[nf >> 1][(nf & 1) * 2], vf[nf >> 1][(nf & 1) * 2 + 1]);
#pragma unroll
            for (int mf = 0; mf < 2; mf++)
#pragma unroll
                for (int nf = 0; nf < 8; nf++)
                    mmah(o[mf][nf], aPl[mf][kk],
                         vf[nf >> 1][(nf & 1) * 2], vf[nf >> 1][(nf & 1) * 2 + 1]);
        }
        __syncthreads();
    }

    int b = bh >> 4, h = bh & 15;
    int colBase = h * 64 + (lane & 3) * 2;
#pragma unroll
    for (int mf = 0; mf < 2; mf++) {
        float lA = ls[mf][0], lB = ls[mf][1];
        lA += __shfl_xor_sync(0xffffffffu, lA, 1);
        lA += __shfl_xor_sync(0xffffffffu, lA, 2);
        lB += __shfl_xor_sync(0xffffffffu, lB, 1);
        lB += __shfl_xor_sync(0xffffffffu, lB, 2);
        float invA = 1.f / lA, invB = 1.f / lB;
        int rowA = b * 2048 + q0 + w * 32 + mf * 16 + (lane >> 2);
#pragma unroll
        for (int nf = 0; nf < 8; nf++) {
            int col = colBase + nf * 8;
            *(uint32_t*)(g_aof + (size_t)rowA * 1024 + col) =
                pack_h2(o[mf][nf][0] * invA, o[mf][nf][1] * invA);
            *(uint32_t*)(g_aof + (size_t)(rowA + 8) * 1024 + col) =
                pack_h2(o[mf][nf][2] * invB, o[mf][nf][3] * invB);
        }
    }
}

// ======================= launch (fork/join streams for graph capture) =======================
extern "C" void kernel_launch(void* const* d_in, const int* in_sizes, int n_in,
                              void* d_out, int out_size) {
    const float* x = (const float*)d_in[0];
    const float* Wqkv = (const float*)d_in[1];
    const float* Wout = (const float*)d_in[2];
    float* out = (float*)d_out;

    void *p_xf, *p_wqf, *p_aof, *p_wof;
    cudaGetSymbolAddress(&p_xf,  g_xf);
    cudaGetSymbolAddress(&p_wqf, g_wqf);
    cudaGetSymbolAddress(&p_aof, g_aof);
    cudaGetSymbolAddress(&p_wof, g_wof);

    cudaFuncSetAttribute(gemm_mma_kernel<0>, cudaFuncAttributeMaxDynamicSharedMemorySize, GEMM_SMEM);
    cudaFuncSetAttribute(gemm_mma_kernel<1>, cudaFuncAttributeMaxDynamicSharedMemorySize, GEMM_SMEM);
    cudaFuncSetAttribute(flash_tc_kernel, cudaFuncAttributeMaxDynamicSharedMemorySize, FLASH_SMEM);

    // Lazy static side stream + events (created on first, uncaptured, call).
    static cudaStream_t s2 = nullptr;
    static cudaEvent_t eStart = nullptr, eQK = nullptr, eWO = nullptr;
    if (!s2) {
        cudaStreamCreateWithFlags(&s2, cudaStreamNonBlocking);
        cudaEventCreateWithFlags(&eStart, cudaEventDisableTiming);
        cudaEventCreateWithFlags(&eQK, cudaEventDisableTiming);
        cudaEventCreateWithFlags(&eWO, cudaEventDisableTiming);
    }

    // Fork: side stream does rope table + both weight transposes.
    cudaEventRecord(eStart, 0);
    cudaStreamWaitEvent(s2, eStart, 0);

    rope_table_kernel<<<256, 256, 0, s2>>>();
    trans_f16_kernel<<<dim3(QKV_N / 32, D_MODEL / 32), dim3(32, 8), 0, s2>>>(
        Wqkv, (__half*)p_wqf, D_MODEL, QKV_N);
    cudaEventRecord(eQK, s2);
    trans_f16_kernel<<<dim3(D_MODEL / 32, D_MODEL / 32), dim3(32, 8), 0, s2>>>(
        Wout, (__half*)p_wof, D_MODEL, D_MODEL);
    cudaEventRecord(eWO, s2);

    // Main stream: x conversion overlaps the side stream.
    conv_f16_kernel<<<4096, 256>>>(x, (__half*)p_xf, M_ROWS * D_MODEL);
    cudaStreamWaitEvent(0, eQK, 0);       // need rope table + Wqkv^T

    gemm_mma_kernel<0><<<dim3(QKV_N / 128, M_ROWS / 128), 128, GEMM_SMEM>>>(
        (const __half*)p_xf, (const __half*)p_wqf, nullptr);

    flash_tc_kernel<<<dim3(16, 64), 128, FLASH_SMEM>>>();

    cudaStreamWaitEvent(0, eWO, 0);       // join: Wout^T ready (ran under gemm<0>/flash)
    gemm_mma_kernel<1><<<dim3(D_MODEL / 128, M_ROWS / 128), 128, GEMM_SMEM>>>(
        (const __half*)p_aof, (const __half*)p_wof, out);
}

// round 14
// speedup vs baseline: 1.1105x; 1.1105x over previous
#include <cuda_runtime.h>
#include <cuda_bf16.h>
#include <cuda_fp16.h>
#include <math.h>
#include <stdint.h>

#define D_MODEL 1024
#define N_HEADS 16
#define HEAD_DIM 64
#define BATCH 4
#define SEQ 2048
#define M_ROWS (BATCH * SEQ)          // 8192
#define QKV_N (3 * D_MODEL)           // 3072

// ======================= scratch (static device globals) =======================
__device__ __align__(16) float g_cos[SEQ * 32];
__device__ __align__(16) float g_sin[SEQ * 32];
__device__ __align__(16) __half g_xf[M_ROWS * D_MODEL];
__device__ __align__(16) __half g_wqf[D_MODEL * QKV_N];       // transposed [3072][1024]
__device__ __align__(16) __half g_aof[M_ROWS * D_MODEL];
__device__ __align__(16) __half g_wof[D_MODEL * D_MODEL];     // transposed [1024][1024]
__device__ __align__(16) __nv_bfloat16 g_qh[BATCH * N_HEADS * SEQ * HEAD_DIM];
__device__ __align__(16) __nv_bfloat16 g_ql[BATCH * N_HEADS * SEQ * HEAD_DIM];
__device__ __align__(16) __nv_bfloat16 g_kh[BATCH * N_HEADS * SEQ * HEAD_DIM];
__device__ __align__(16) __nv_bfloat16 g_kl[BATCH * N_HEADS * SEQ * HEAD_DIM];
__device__ __align__(16) __half g_vf[BATCH * N_HEADS * SEQ * HEAD_DIM];

// ======================= PTX helpers =======================
__device__ __forceinline__ uint32_t smem_to_u32(const void* smem_ptr) {
    uint32_t addr;
    asm("{ .reg .u64 tmp; cvta.to.shared.u64 tmp, %1; cvt.u32.u64 %0, tmp; }"
        : "=r"(addr) : "l"(smem_ptr));
    return addr;
}
__device__ __forceinline__ void cpa16(uint32_t s, const void* g) {
    asm volatile("cp.async.cg.shared.global [%0], [%1], 16;" :: "r"(s), "l"(g));
}
__device__ __forceinline__ void cpa_commit() {
    asm volatile("cp.async.commit_group;" ::: "memory");
}
__device__ __forceinline__ void ldsm4(uint32_t* r, uint32_t addr) {
    asm volatile("ldmatrix.sync.aligned.m8n8.x4.shared.b16 {%0,%1,%2,%3}, [%4];"
        : "=r"(r[0]), "=r"(r[1]), "=r"(r[2]), "=r"(r[3]) : "r"(addr));
}
__device__ __forceinline__ void ldsm4t(uint32_t* r, uint32_t addr) {
    asm volatile("ldmatrix.sync.aligned.m8n8.x4.trans.shared.b16 {%0,%1,%2,%3}, [%4];"
        : "=r"(r[0]), "=r"(r[1]), "=r"(r[2]), "=r"(r[3]) : "r"(addr));
}
__device__ __forceinline__ void mma16816(float* c, const uint32_t* a, uint32_t b0, uint32_t b1) {
    asm("mma.sync.aligned.m16n8k16.row.col.f32.bf16.bf16.f32 "
        "{%0,%1,%2,%3}, {%4,%5,%6,%7}, {%8,%9}, {%0,%1,%2,%3};"
        : "+f"(c[0]), "+f"(c[1]), "+f"(c[2]), "+f"(c[3])
        : "r"(a[0]), "r"(a[1]), "r"(a[2]), "r"(a[3]), "r"(b0), "r"(b1));
}
__device__ __forceinline__ void mmah(float* c, const uint32_t* a, uint32_t b0, uint32_t b1) {
    asm("mma.sync.aligned.m16n8k16.row.col.f32.f16.f16.f32 "
        "{%0,%1,%2,%3}, {%4,%5,%6,%7}, {%8,%9}, {%0,%1,%2,%3};"
        : "+f"(c[0]), "+f"(c[1]), "+f"(c[2]), "+f"(c[3])
        : "r"(a[0]), "r"(a[1]), "r"(a[2]), "r"(a[3]), "r"(b0), "r"(b1));
}
__device__ __forceinline__ uint32_t pack_h2(float a, float b) {
    __half2 h = __floats2half2_rn(a, b);
    return *(uint32_t*)&h;
}
__device__ __forceinline__ uint32_t pack_bf2(float a, float b) {
    __nv_bfloat162 h = __floats2bfloat162_rn(a, b);
    return *(uint32_t*)&h;
}
__device__ __forceinline__ float ex2f(float x) {
    float r;
    asm("ex2.approx.ftz.f32 %0, %1;" : "=f"(r) : "f"(x));
    return r;
}

// ======================= RoPE table (fp32) =======================
__global__ void rope_table_kernel() {
    int idx = blockIdx.x * blockDim.x + threadIdx.x;   // 0..65535
    int t = idx >> 5;
    int i = idx & 31;
    float inv = exp2f(-(float)(2 * i) * (1.0f / 64.0f) * 13.28771237954945f); // log2(10000)
    float a = (float)t * inv;
    float s, c;
    sincosf(a, &s, &c);
    g_cos[t * 32 + i] = c;
    g_sin[t * 32 + i] = s;
}

// ======================= fp32 -> fp16 =======================
__global__ void conv_f16_kernel(const float* __restrict__ in,
                                __half* __restrict__ out, int n) {
    int i = blockIdx.x * blockDim.x + threadIdx.x;
    int stride = gridDim.x * blockDim.x;
    for (; i < n; i += stride) out[i] = __float2half_rn(in[i]);
}

// ======================= transpose fp32 -> fp16 =======================
__global__ void trans_f16_kernel(const float* __restrict__ W,
                                 __half* __restrict__ T, int K, int N) {
    __shared__ float t[32][33];
    int n = blockIdx.x * 32 + threadIdx.x;
    int k0 = blockIdx.y * 32;
#pragma unroll
    for (int r = 0; r < 32; r += 8)
        t[threadIdx.y + r][threadIdx.x] = W[(size_t)(k0 + threadIdx.y + r) * N + n];
    __syncthreads();
    int k = k0 + threadIdx.x;
#pragma unroll
    for (int r = 0; r < 32; r += 8) {
        int n2 = blockIdx.x * 32 + threadIdx.y + r;
        T[(size_t)n2 * K + k] = __float2half_rn(t[threadIdx.x][threadIdx.y + r]);
    }
}

// ======================= fp16 warp-MMA GEMM, K-stage 64, 4 warps (2x2) ==============
#define GTILE 18432                     // 128 rows * 144B
#define GSTG  (2 * GTILE)               // A + B per stage
#define GEMM_SMEM (2 * GSTG)            // 73728 (double buffered)

__device__ __forceinline__ void load_stage(
    uint32_t sb, const __half* __restrict__ Ah, const __half* __restrict__ Bh,
    int m0, int n0, int k0, int tid)
{
    const __half* gp[2] = { Ah, Bh };
    int rb[2] = { m0, n0 };
#pragma unroll
    for (int i = 0; i < 16; i++) {
        int ch = tid + i * 128;              // 0..2047
        int tlb = ch >> 10;
        int w2 = ch & 1023;
        int row = w2 >> 3, c16 = w2 & 7;
        cpa16(sb + tlb * GTILE + row * 144 + c16 * 16,
              gp[tlb] + (size_t)(rb[tlb] + row) * 1024 + k0 + c16 * 8);
    }
}

template <int EPI>  // 0: RoPE+split scatter to qh/ql/kh/kl + fp16 V, 1: plain fp32 store
__global__ void __launch_bounds__(128, 2) gemm_mma_kernel(
    const __half* __restrict__ Ah, const __half* __restrict__ Bh,
    float* __restrict__ Cout)
{
    extern __shared__ char dsm[];
    uint32_t sb0 = smem_to_u32(dsm);
    int tid = threadIdx.x, lane = tid & 31, wid = tid >> 5;
    int warpM = wid >> 1, warpN = wid & 1;      // 2 x 2
    int m0 = blockIdx.y * 128, n0 = blockIdx.x * 128;

    float c[4][8][4];
#pragma unroll
    for (int i = 0; i < 4; i++)
#pragma unroll
        for (int j = 0; j < 8; j++)
#pragma unroll
            for (int k = 0; k < 4; k++) c[i][j][k] = 0.f;

    uint32_t aRow = (uint32_t)((warpM * 64 + (lane & 15)) * 144 + ((lane >> 4) << 4));
    uint32_t bRow = (uint32_t)((warpN * 64 + ((lane >> 4) << 3) + (lane & 7)) * 144 +
                               (((lane >> 3) & 1) << 4));

    const int NS = 16;
    load_stage(sb0, Ah, Bh, m0, n0, 0, tid);
    cpa_commit();

    for (int s = 0; s < NS; s++) {
        uint32_t sb = sb0 + (uint32_t)((s & 1) * GSTG);
        if (s + 1 < NS) {
            load_stage(sb0 + (uint32_t)(((s + 1) & 1) * GSTG),
                       Ah, Bh, m0, n0, (s + 1) * 64, tid);
            cpa_commit();
            asm volatile("cp.async.wait_group 1;" ::: "memory");
        } else {
            asm volatile("cp.async.wait_group 0;" ::: "memory");
        }
        __syncthreads();

#pragma unroll
        for (int k16 = 0; k16 < 4; k16++) {
            uint32_t koff = (uint32_t)(k16 * 32);
            uint32_t af[4][4], bf[4][4];
#pragma unroll
            for (int mf = 0; mf < 4; mf++)
                ldsm4(af[mf], sb + aRow + (uint32_t)(mf * 2304) + koff);
#pragma unroll
            for (int nf2 = 0; nf2 < 4; nf2++)
                ldsm4(bf[nf2], sb + GTILE + bRow + (uint32_t)(nf2 * 2304) + koff);
#pragma unroll
            for (int mf = 0; mf < 4; mf++)
#pragma unroll
                for (int nf = 0; nf < 8; nf++)
                    mmah(c[mf][nf], af[mf],
                         bf[nf >> 1][(nf & 1) * 2], bf[nf >> 1][(nf & 1) * 2 + 1]);
        }
        __syncthreads();
    }

    // ---------------- epilogue ----------------
    int mBase = m0 + warpM * 64 + (lane >> 2);
    if (EPI == 1) {
        int nBase = n0 + warpN * 64 + (lane & 3) * 2;
#pragma unroll
        for (int mf = 0; mf < 4; mf++)
#pragma unroll
            for (int nf = 0; nf < 8; nf++) {
                int row = mBase + mf * 16;
                int col = nBase + nf * 8;
                *(float2*)(Cout + (size_t)row * 1024 + col) =
                    make_float2(c[mf][nf][0], c[mf][nf][1]);
                *(float2*)(Cout + (size_t)(row + 8) * 1024 + col) =
                    make_float2(c[mf][nf][2], c[mf][nf][3]);
            }
        return;
    }

    // EPI==0: this warp's 64-col span = exactly one (sel, head)
    int col0 = n0 + warpN * 64;
    int sel = col0 >> 10;                 // 0:Q 1:K 2:V
    int h = (col0 >> 6) & 15;
    int lc = (lane & 3) * 2;

    if (sel == 2) {
#pragma unroll
        for (int mf = 0; mf < 4; mf++) {
            int row = mBase + mf * 16;
            int b = row >> 11, t = row & 2047;
            size_t base = ((size_t)((b * 16 + h) * 2048)) * 64;
#pragma unroll
            for (int nf = 0; nf < 8; nf++) {
                int d = lc + nf * 8;
                *(uint32_t*)(g_vf + base + (size_t)t * 64 + d) =
                    pack_h2(c[mf][nf][0], c[mf][nf][1]);
                *(uint32_t*)(g_vf + base + (size_t)(t + 8) * 64 + d) =
                    pack_h2(c[mf][nf][2], c[mf][nf][3]);
            }
        }
    } else {
        const float SCQ = 0.125f * 1.44269504088896f;
        float scale = (sel == 0) ? SCQ : 1.f;
        __nv_bfloat16* Gh = (sel == 0) ? g_qh : g_kh;
        __nv_bfloat16* Gl = (sel == 0) ? g_ql : g_kl;
#pragma unroll
        for (int mf = 0; mf < 4; mf++) {
            int row = mBase + mf * 16;
            int b = row >> 11, t = row & 2047;
            size_t base = ((size_t)((b * 16 + h) * 2048)) * 64;
#pragma unroll
            for (int nfp = 0; nfp < 4; nfp++) {
                int i0 = lc + nfp * 8;
                float2 cs0 = *(const float2*)&g_cos[t * 32 + i0];
                float2 sn0 = *(const float2*)&g_sin[t * 32 + i0];
                float2 cs8 = *(const float2*)&g_cos[(t + 8) * 32 + i0];
                float2 sn8 = *(const float2*)&g_sin[(t + 8) * 32 + i0];
#pragma unroll
                for (int rr = 0; rr < 2; rr++) {
                    float cx = rr ? cs8.x : cs0.x, cy = rr ? cs8.y : cs0.y;
                    float sx = rr ? sn8.x : sn0.x, sy = rr ? sn8.y : sn0.y;
                    float x1a = c[mf][nfp][rr * 2],     x1b = c[mf][nfp][rr * 2 + 1];
                    float x2a = c[mf][nfp + 4][rr * 2], x2b = c[mf][nfp + 4][rr * 2 + 1];
                    float r1a = (x1a * cx - x2a * sx) * scale;
                    float r1b = (x1b * cy - x2b * sy) * scale;
                    float r2a = (x2a * cx + x1a * sx) * scale;
                    float r2b = (x2b * cy + x1b * sy) * scale;
                    __nv_bfloat16 h1a = __float2bfloat16(r1a), h1b = __float2bfloat16(r1b);
                    __nv_bfloat16 h2a = __float2bfloat16(r2a), h2b = __float2bfloat16(r2b);
                    size_t off = base + (size_t)(t + rr * 8) * 64 + i0;
                    *(uint32_t*)(Gh + off) =
                        ((uint32_t)*(uint16_t*)&h1a) | (((uint32_t)*(uint16_t*)&h1b) << 16);
                    *(uint32_t*)(Gh + off + 32) =
                        ((uint32_t)*(uint16_t*)&h2a) | (((uint32_t)*(uint16_t*)&h2b) << 16);
                    *(uint32_t*)(Gl + off) =
                        pack_bf2(r1a - __bfloat162float(h1a), r1b - __bfloat162float(h1b));
                    *(uint32_t*)(Gl + off + 32) =
                        pack_bf2(r2a - __bfloat162float(h2a), r2b - __bfloat162float(h2b));
                }
            }
        }
    }
}

// ======================= Tensor-core flash: 4 warps x 32 q-rows =======================
// S = QK^T : 3-term bf16.  O = PV : single-term fp16 (P fp16, V fp16).
#define FRS 144
#define FTILE (64 * FRS)                 // 9216
#define FQ_B  (128 * FRS)                // 18432
#define FSB_Q 0
#define FSB_KV (2 * FQ_B)                // 36864
#define FSTG_B (3 * FTILE)               // Khi, Klo, Vf = 27648
#define FLASH_SMEM (FSB_KV + 2 * FSTG_B) // 92160

__device__ __forceinline__ void flash_load_q(uint32_t sb, int bh, int q0, int tid) {
#pragma unroll
    for (int i = 0; i < 16; i++) {
        int ch = tid + i * 128;               // 0..2047
        int tl = ch >> 10;
        int r = (ch >> 3) & 127, c16 = ch & 7;
        const __nv_bfloat16* src = (tl ? g_ql : g_qh) +
            ((size_t)bh * SEQ + q0 + r) * 64 + c16 * 8;
        cpa16(sb + FSB_Q + tl * FQ_B + r * FRS + c16 * 16, src);
    }
}
__device__ __forceinline__ void flash_load_kv(uint32_t sb, int bh, int kbase, int stg, int tid) {
    uint32_t d0 = sb + FSB_KV + stg * FSTG_B;
#pragma unroll
    for (int i = 0; i < 12; i++) {
        int ch = tid + i * 128;               // 0..1535
        int tl = ch >> 9;                     // 0 Khi, 1 Klo, 2 Vf
        int r = (ch >> 3) & 63, c16 = ch & 7;
        const void* src;
        if (tl == 0)      src = g_kh + ((size_t)bh * SEQ + kbase + r) * 64 + c16 * 8;
        else if (tl == 1) src = g_kl + ((size_t)bh * SEQ + kbase + r) * 64 + c16 * 8;
        else              src = g_vf + ((size_t)bh * SEQ + kbase + r) * 64 + c16 * 8;
        cpa16(d0 + tl * FTILE + r * FRS + c16 * 16, src);
    }
}

__global__ void __launch_bounds__(128, 2) flash_tc_kernel() {
    extern __shared__ char dsm[];
    uint32_t sb = smem_to_u32(dsm);
    int tid = threadIdx.x, lane = tid & 31, w = tid >> 5;
    int qt = 15 - (int)blockIdx.x;
    int bh = blockIdx.y;
    int q0 = qt * 128;
    int nkt = qt * 2 + 2;

    flash_load_q(sb, bh, q0, tid);
    flash_load_kv(sb, bh, 0, 0, tid);
    cpa_commit();

    uint32_t aQh[2][4][4], aQl[2][4][4];
    float o[2][8][4];
#pragma unroll
    for (int mf = 0; mf < 2; mf++)
#pragma unroll
        for (int i = 0; i < 8; i++)
#pragma unroll
            for (int j = 0; j < 4; j++) o[mf][i][j] = 0.f;
    float ls[2][2] = {{0.f, 0.f}, {0.f, 0.f}};

    uint32_t qAddr = (uint32_t)((w * 32 + (lane & 15)) * FRS + ((lane >> 4) << 4));
    uint32_t kLane = (uint32_t)((((lane >> 4) << 3) + (lane & 7)) * FRS + (((lane >> 3) & 1) << 4));
    uint32_t vLane = (uint32_t)(((lane & 7) + ((lane >> 3) & 1) * 8) * FRS + ((lane >> 4) << 4));

    for (int kt = 0; kt < nkt; kt++) {
        if (kt + 1 < nkt) {
            flash_load_kv(sb, bh, (kt + 1) * 64, (kt + 1) & 1, tid);
            cpa_commit();
            asm volatile("cp.async.wait_group 1;" ::: "memory");
        } else {
            asm volatile("cp.async.wait_group 0;" ::: "memory");
        }
        __syncthreads();

        if (kt == 0) {
#pragma unroll
            for (int mf = 0; mf < 2; mf++)
#pragma unroll
                for (int kk = 0; kk < 4; kk++) {
                    uint32_t a = sb + FSB_Q + qAddr + (uint32_t)(mf * 16 * FRS) + kk * 32;
                    ldsm4(aQh[mf][kk], a);
                    ldsm4(aQl[mf][kk], a + FQ_B);
                }
        }

        uint32_t stg = sb + FSB_KV + (kt & 1) * FSTG_B;
        int kbase = kt * 64;

        // ---- S = Q K^T (3-term bf16, term-major per kk) ----
        float c[2][8][4];
#pragma unroll
        for (int mf = 0; mf < 2; mf++)
#pragma unroll
            for (int i = 0; i < 8; i++)
#pragma unroll
                for (int j = 0; j < 4; j++) c[mf][i][j] = 0.f;

#pragma unroll
        for (int kk = 0; kk < 4; kk++) {
            uint32_t bKh[4][4], bKl[4][4];
#pragma unroll
            for (int nf2 = 0; nf2 < 4; nf2++) {
                uint32_t ba = stg + (uint32_t)(nf2 * 16 * FRS) + kLane + kk * 32;
                ldsm4(bKh[nf2], ba);
                ldsm4(bKl[nf2], ba + FTILE);
            }
#pragma unroll
            for (int mf = 0; mf < 2; mf++)
#pragma unroll
                for (int nf = 0; nf < 8; nf++)
                    mma16816(c[mf][nf], aQh[mf][kk],
                             bKh[nf >> 1][(nf & 1) * 2], bKh[nf >> 1][(nf & 1) * 2 + 1]);
#pragma unroll
            for (int mf = 0; mf < 2; mf++)
#pragma unroll
                for (int nf = 0; nf < 8; nf++)
                    mma16816(c[mf][nf], aQh[mf][kk],
                             bKl[nf >> 1][(nf & 1) * 2], bKl[nf >> 1][(nf & 1) * 2 + 1]);
#pragma unroll
            for (int mf = 0; mf < 2; mf++)
#pragma unroll
                for (int nf = 0; nf < 8; nf++)
                    mma16816(c[mf][nf], aQl[mf][kk],
                             bKh[nf >> 1][(nf & 1) * 2], bKh[nf >> 1][(nf & 1) * 2 + 1]);
        }

        // ---- mask + exp + pack P (single fp16) ----
        bool needmask = (kbase + 63) > (q0 + w * 32);
        uint32_t aPh[2][4][4];
#pragma unroll
        for (int mf = 0; mf < 2; mf++) {
            int qrA = q0 + w * 32 + mf * 16 + (lane >> 2);
#pragma unroll
            for (int nf = 0; nf < 8; nf++) {
                if (needmask) {
                    int key0 = kbase + nf * 8 + (lane & 3) * 2;
                    if (key0 > qrA)         c[mf][nf][0] = -100000.f;
                    if (key0 + 1 > qrA)     c[mf][nf][1] = -100000.f;
                    if (key0 > qrA + 8)     c[mf][nf][2] = -100000.f;
                    if (key0 + 1 > qrA + 8) c[mf][nf][3] = -100000.f;
                }
                float p0 = ex2f(c[mf][nf][0]), p1 = ex2f(c[mf][nf][1]);
                float p2 = ex2f(c[mf][nf][2]), p3 = ex2f(c[mf][nf][3]);
                ls[mf][0] += p0 + p1;
                ls[mf][1] += p2 + p3;
                int kk = nf >> 1, sl = (nf & 1) * 2;
                aPh[mf][kk][sl]     = pack_h2(p0, p1);
                aPh[mf][kk][sl + 1] = pack_h2(p2, p3);
            }
        }

        // ---- O += P V (single-term fp16, term-major per kk) ----
        uint32_t vstg = stg + 2 * FTILE;
#pragma unroll
        for (int kk = 0; kk < 4; kk++) {
            uint32_t vf[4][4];
#pragma unroll
            for (int df2 = 0; df2 < 4; df2++)
                ldsm4t(vf[df2], vstg + (uint32_t)(kk * 16 * FRS) + vLane + df2 * 32);
#pragma unroll
            for (int mf = 0; mf < 2; mf++)
#pragma unroll
                for (int nf = 0; nf < 8; nf++)
                    mmah(o[mf][nf], aPh[mf][kk],
                         vf[nf >> 1][(nf & 1) * 2], vf[nf >> 1][(nf & 1) * 2 + 1]);
        }
        __syncthreads();
    }

    int b = bh >> 4, h = bh & 15;
    int colBase = h * 64 + (lane & 3) * 2;
#pragma unroll
    for (int mf = 0; mf < 2; mf++) {
        float lA = ls[mf][0], lB = ls[mf][1];
        lA += __shfl_xor_sync(0xffffffffu, lA, 1);
        lA += __shfl_xor_sync(0xffffffffu, lA, 2);
        lB += __shfl_xor_sync(0xffffffffu, lB, 1);
        lB += __shfl_xor_sync(0xffffffffu, lB, 2);
        float invA = 1.f / lA, invB = 1.f / lB;
        int rowA = b * 2048 + q0 + w * 32 + mf * 16 + (lane >> 2);
#pragma unroll
        for (int nf = 0; nf < 8; nf++) {
            int col = colBase + nf * 8;
            *(uint32_t*)(g_aof + (size_t)rowA * 1024 + col) =
                pack_h2(o[mf][nf][0] * invA, o[mf][nf][1] * invA);
            *(uint32_t*)(g_aof + (size_t)(rowA + 8) * 1024 + col) =
                pack_h2(o[mf][nf][2] * invB, o[mf][nf][3] * invB);
        }
    }
}

// ======================= launch (fork/join streams for graph capture) =======================
extern "C" void kernel_launch(void* const* d_in, const int* in_sizes, int n_in,
                              void* d_out, int out_size) {
    const float* x = (const float*)d_in[0];
    const float* Wqkv = (const float*)d_in[1];
    const float* Wout = (const float*)d_in[2];
    float* out = (float*)d_out;

    void *p_xf, *p_wqf, *p_aof, *p_wof;
    cudaGetSymbolAddress(&p_xf,  g_xf);
    cudaGetSymbolAddress(&p_wqf, g_wqf);
    cudaGetSymbolAddress(&p_aof, g_aof);
    cudaGetSymbolAddress(&p_wof, g_wof);

    cudaFuncSetAttribute(gemm_mma_kernel<0>, cudaFuncAttributeMaxDynamicSharedMemorySize, GEMM_SMEM);
    cudaFuncSetAttribute(gemm_mma_kernel<1>, cudaFuncAttributeMaxDynamicSharedMemorySize, GEMM_SMEM);
    cudaFuncSetAttribute(flash_tc_kernel, cudaFuncAttributeMaxDynamicSharedMemorySize, FLASH_SMEM);

    static cudaStream_t s2 = nullptr;
    static cudaEvent_t eStart = nullptr, eQK = nullptr, eWO = nullptr;
    if (!s2) {
        cudaStreamCreateWithFlags(&s2, cudaStreamNonBlocking);
        cudaEventCreateWithFlags(&eStart, cudaEventDisableTiming);
        cudaEventCreateWithFlags(&eQK, cudaEventDisableTiming);
        cudaEventCreateWithFlags(&eWO, cudaEventDisableTiming);
    }

    cudaEventRecord(eStart, 0);
    cudaStreamWaitEvent(s2, eStart, 0);

    rope_table_kernel<<<256, 256, 0, s2>>>();
    trans_f16_kernel<<<dim3(QKV_N / 32, D_MODEL / 32), dim3(32, 8), 0, s2>>>(
        Wqkv, (__half*)p_wqf, D_MODEL, QKV_N);
    cudaEventRecord(eQK, s2);
    trans_f16_kernel<<<dim3(D_MODEL / 32, D_MODEL / 32), dim3(32, 8), 0, s2>>>(
        Wout, (__half*)p_wof, D_MODEL, D_MODEL);
    cudaEventRecord(eWO, s2);

    conv_f16_kernel<<<4096, 256>>>(x, (__half*)p_xf, M_ROWS * D_MODEL);
    cudaStreamWaitEvent(0, eQK, 0);

    gemm_mma_kernel<0><<<dim3(QKV_N / 128, M_ROWS / 128), 128, GEMM_SMEM>>>(
        (const __half*)p_xf, (const __half*)p_wqf, nullptr);

    flash_tc_kernel<<<dim3(16, 64), 128, FLASH_SMEM>>>();

    cudaStreamWaitEvent(0, eWO, 0);
    gemm_mma_kernel<1><<<dim3(D_MODEL / 128, M_ROWS / 128), 128, GEMM_SMEM>>>(
        (const __half*)p_aof, (const __half*)p_wof, out);
}

// round 15
// speedup vs baseline: 1.3880x; 1.2498x over previous
#include <cuda_runtime.h>
#include <cuda_fp16.h>
#include <math.h>
#include <stdint.h>

#define D_MODEL 1024
#define N_HEADS 16
#define HEAD_DIM 64
#define BATCH 4
#define SEQ 2048
#define M_ROWS (BATCH * SEQ)          // 8192
#define QKV_N (3 * D_MODEL)           // 3072

// ======================= scratch (static device globals) =======================
__device__ __align__(16) float g_cos[SEQ * 32];
__device__ __align__(16) float g_sin[SEQ * 32];
__device__ __align__(16) __half g_xf[M_ROWS * D_MODEL];
__device__ __align__(16) __half g_wqf[D_MODEL * QKV_N];       // transposed [3072][1024]
__device__ __align__(16) __half g_aof[M_ROWS * D_MODEL];
__device__ __align__(16) __half g_wof[D_MODEL * D_MODEL];     // transposed [1024][1024]
__device__ __align__(16) __half g_qf[BATCH * N_HEADS * SEQ * HEAD_DIM];
__device__ __align__(16) __half g_kf[BATCH * N_HEADS * SEQ * HEAD_DIM];
__device__ __align__(16) __half g_vf[BATCH * N_HEADS * SEQ * HEAD_DIM];

// ======================= PTX helpers =======================
__device__ __forceinline__ uint32_t smem_to_u32(const void* smem_ptr) {
    uint32_t addr;
    asm("{ .reg .u64 tmp; cvta.to.shared.u64 tmp, %1; cvt.u32.u64 %0, tmp; }"
        : "=r"(addr) : "l"(smem_ptr));
    return addr;
}
__device__ __forceinline__ void cpa16(uint32_t s, const void* g) {
    asm volatile("cp.async.cg.shared.global [%0], [%1], 16;" :: "r"(s), "l"(g));
}
__device__ __forceinline__ void cpa_commit() {
    asm volatile("cp.async.commit_group;" ::: "memory");
}
__device__ __forceinline__ void ldsm4(uint32_t* r, uint32_t addr) {
    asm volatile("ldmatrix.sync.aligned.m8n8.x4.shared.b16 {%0,%1,%2,%3}, [%4];"
        : "=r"(r[0]), "=r"(r[1]), "=r"(r[2]), "=r"(r[3]) : "r"(addr));
}
__device__ __forceinline__ void ldsm4t(uint32_t* r, uint32_t addr) {
    asm volatile("ldmatrix.sync.aligned.m8n8.x4.trans.shared.b16 {%0,%1,%2,%3}, [%4];"
        : "=r"(r[0]), "=r"(r[1]), "=r"(r[2]), "=r"(r[3]) : "r"(addr));
}
__device__ __forceinline__ void mmah(float* c, const uint32_t* a, uint32_t b0, uint32_t b1) {
    asm("mma.sync.aligned.m16n8k16.row.col.f32.f16.f16.f32 "
        "{%0,%1,%2,%3}, {%4,%5,%6,%7}, {%8,%9}, {%0,%1,%2,%3};"
        : "+f"(c[0]), "+f"(c[1]), "+f"(c[2]), "+f"(c[3])
        : "r"(a[0]), "r"(a[1]), "r"(a[2]), "r"(a[3]), "r"(b0), "r"(b1));
}
__device__ __forceinline__ uint32_t pack_h2(float a, float b) {
    __half2 h = __floats2half2_rn(a, b);
    return *(uint32_t*)&h;
}
__device__ __forceinline__ float ex2f(float x) {
    float r;
    asm("ex2.approx.ftz.f32 %0, %1;" : "=f"(r) : "f"(x));
    return r;
}

// ======================= RoPE table (fp32) =======================
__global__ void rope_table_kernel() {
    int idx = blockIdx.x * blockDim.x + threadIdx.x;   // 0..65535
    int t = idx >> 5;
    int i = idx & 31;
    float inv = exp2f(-(float)(2 * i) * (1.0f / 64.0f) * 13.28771237954945f); // log2(10000)
    float a = (float)t * inv;
    float s, c;
    sincosf(a, &s, &c);
    g_cos[t * 32 + i] = c;
    g_sin[t * 32 + i] = s;
}

// ======================= fp32 -> fp16 =======================
__global__ void conv_f16_kernel(const float* __restrict__ in,
                                __half* __restrict__ out, int n) {
    int i = blockIdx.x * blockDim.x + threadIdx.x;
    int stride = gridDim.x * blockDim.x;
    for (; i < n; i += stride) out[i] = __float2half_rn(in[i]);
}

// ======================= transpose fp32 -> fp16 =======================
__global__ void trans_f16_kernel(const float* __restrict__ W,
                                 __half* __restrict__ T, int K, int N) {
    __shared__ float t[32][33];
    int n = blockIdx.x * 32 + threadIdx.x;
    int k0 = blockIdx.y * 32;
#pragma unroll
    for (int r = 0; r < 32; r += 8)
        t[threadIdx.y + r][threadIdx.x] = W[(size_t)(k0 + threadIdx.y + r) * N + n];
    __syncthreads();
    int k = k0 + threadIdx.x;
#pragma unroll
    for (int r = 0; r < 32; r += 8) {
        int n2 = blockIdx.x * 32 + threadIdx.y + r;
        T[(size_t)n2 * K + k] = __float2half_rn(t[threadIdx.x][threadIdx.y + r]);
    }
}

// ======================= fp16 warp-MMA GEMM, K-stage 64, 4 warps (2x2) ==============
#define GTILE 18432                     // 128 rows * 144B
#define GSTG  (2 * GTILE)               // A + B per stage
#define GEMM_SMEM (2 * GSTG)            // 73728 (double buffered)

__device__ __forceinline__ void load_stage(
    uint32_t sb, const __half* __restrict__ Ah, const __half* __restrict__ Bh,
    int m0, int n0, int k0, int tid)
{
    const __half* gp[2] = { Ah, Bh };
    int rb[2] = { m0, n0 };
#pragma unroll
    for (int i = 0; i < 16; i++) {
        int ch = tid + i * 128;              // 0..2047
        int tlb = ch >> 10;
        int w2 = ch & 1023;
        int row = w2 >> 3, c16 = w2 & 7;
        cpa16(sb + tlb * GTILE + row * 144 + c16 * 16,
              gp[tlb] + (size_t)(rb[tlb] + row) * 1024 + k0 + c16 * 8);
    }
}

template <int EPI>  // 0: RoPE + fp16 scatter to qf/kf/vf, 1: plain fp32 store
__global__ void __launch_bounds__(128, 2) gemm_mma_kernel(
    const __half* __restrict__ Ah, const __half* __restrict__ Bh,
    float* __restrict__ Cout)
{
    extern __shared__ char dsm[];
    uint32_t sb0 = smem_to_u32(dsm);
    int tid = threadIdx.x, lane = tid & 31, wid = tid >> 5;
    int warpM = wid >> 1, warpN = wid & 1;      // 2 x 2
    int m0 = blockIdx.y * 128, n0 = blockIdx.x * 128;

    float c[4][8][4];
#pragma unroll
    for (int i = 0; i < 4; i++)
#pragma unroll
        for (int j = 0; j < 8; j++)
#pragma unroll
            for (int k = 0; k < 4; k++) c[i][j][k] = 0.f;

    uint32_t aRow = (uint32_t)((warpM * 64 + (lane & 15)) * 144 + ((lane >> 4) << 4));
    uint32_t bRow = (uint32_t)((warpN * 64 + ((lane >> 4) << 3) + (lane & 7)) * 144 +
                               (((lane >> 3) & 1) << 4));

    const int NS = 16;
    load_stage(sb0, Ah, Bh, m0, n0, 0, tid);
    cpa_commit();

    for (int s = 0; s < NS; s++) {
        uint32_t sb = sb0 + (uint32_t)((s & 1) * GSTG);
        if (s + 1 < NS) {
            load_stage(sb0 + (uint32_t)(((s + 1) & 1) * GSTG),
                       Ah, Bh, m0, n0, (s + 1) * 64, tid);
            cpa_commit();
            asm volatile("cp.async.wait_group 1;" ::: "memory");
        } else {
            asm volatile("cp.async.wait_group 0;" ::: "memory");
        }
        __syncthreads();

#pragma unroll
        for (int k16 = 0; k16 < 4; k16++) {
            uint32_t koff = (uint32_t)(k16 * 32);
            uint32_t af[4][4], bf[4][4];
#pragma unroll
            for (int mf = 0; mf < 4; mf++)
                ldsm4(af[mf], sb + aRow + (uint32_t)(mf * 2304) + koff);
#pragma unroll
            for (int nf2 = 0; nf2 < 4; nf2++)
                ldsm4(bf[nf2], sb + GTILE + bRow + (uint32_t)(nf2 * 2304) + koff);
#pragma unroll
            for (int mf = 0; mf < 4; mf++)
#pragma unroll
                for (int nf = 0; nf < 8; nf++)
                    mmah(c[mf][nf], af[mf],
                         bf[nf >> 1][(nf & 1) * 2], bf[nf >> 1][(nf & 1) * 2 + 1]);
        }
        __syncthreads();
    }

    // ---------------- epilogue ----------------
    int mBase = m0 + warpM * 64 + (lane >> 2);
    if (EPI == 1) {
        int nBase = n0 + warpN * 64 + (lane & 3) * 2;
#pragma unroll
        for (int mf = 0; mf < 4; mf++)
#pragma unroll
            for (int nf = 0; nf < 8; nf++) {
                int row = mBase + mf * 16;
                int col = nBase + nf * 8;
                *(float2*)(Cout + (size_t)row * 1024 + col) =
                    make_float2(c[mf][nf][0], c[mf][nf][1]);
                *(float2*)(Cout + (size_t)(row + 8) * 1024 + col) =
                    make_float2(c[mf][nf][2], c[mf][nf][3]);
            }
        return;
    }

    // EPI==0: this warp's 64-col span = exactly one (sel, head)
    int col0 = n0 + warpN * 64;
    int sel = col0 >> 10;                 // 0:Q 1:K 2:V
    int h = (col0 >> 6) & 15;
    int lc = (lane & 3) * 2;

    if (sel == 2) {
#pragma unroll
        for (int mf = 0; mf < 4; mf++) {
            int row = mBase + mf * 16;
            int b = row >> 11, t = row & 2047;
            size_t base = ((size_t)((b * 16 + h) * 2048)) * 64;
#pragma unroll
            for (int nf = 0; nf < 8; nf++) {
                int d = lc + nf * 8;
                *(uint32_t*)(g_vf + base + (size_t)t * 64 + d) =
                    pack_h2(c[mf][nf][0], c[mf][nf][1]);
                *(uint32_t*)(g_vf + base + (size_t)(t + 8) * 64 + d) =
                    pack_h2(c[mf][nf][2], c[mf][nf][3]);
            }
        }
    } else {
        // Q/K: RoPE in registers, single fp16 store.
        const float SCQ = 0.125f * 1.44269504088896f;
        float scale = (sel == 0) ? SCQ : 1.f;
        __half* G = (sel == 0) ? g_qf : g_kf;
#pragma unroll
        for (int mf = 0; mf < 4; mf++) {
            int row = mBase + mf * 16;
            int b = row >> 11, t = row & 2047;
            size_t base = ((size_t)((b * 16 + h) * 2048)) * 64;
#pragma unroll
            for (int nfp = 0; nfp < 4; nfp++) {
                int i0 = lc + nfp * 8;
                float2 cs0 = *(const float2*)&g_cos[t * 32 + i0];
                float2 sn0 = *(const float2*)&g_sin[t * 32 + i0];
                float2 cs8 = *(const float2*)&g_cos[(t + 8) * 32 + i0];
                float2 sn8 = *(const float2*)&g_sin[(t + 8) * 32 + i0];
#pragma unroll
                for (int rr = 0; rr < 2; rr++) {
                    float cx = rr ? cs8.x : cs0.x, cy = rr ? cs8.y : cs0.y;
                    float sx = rr ? sn8.x : sn0.x, sy = rr ? sn8.y : sn0.y;
                    float x1a = c[mf][nfp][rr * 2],     x1b = c[mf][nfp][rr * 2 + 1];
                    float x2a = c[mf][nfp + 4][rr * 2], x2b = c[mf][nfp + 4][rr * 2 + 1];
                    float r1a = (x1a * cx - x2a * sx) * scale;
                    float r1b = (x1b * cy - x2b * sy) * scale;
                    float r2a = (x2a * cx + x1a * sx) * scale;
                    float r2b = (x2b * cy + x1b * sy) * scale;
                    size_t off = base + (size_t)(t + rr * 8) * 64 + i0;
                    *(uint32_t*)(G + off)      = pack_h2(r1a, r1b);
                    *(uint32_t*)(G + off + 32) = pack_h2(r2a, r2b);
                }
            }
        }
    }
}

// ======================= Tensor-core flash: 4 warps x 32 q-rows =======================
// S = QK^T : single fp16.  O = PV : single fp16. fp32 accum everywhere.
#define FRS 144
#define FTILE (64 * FRS)                 // 9216
#define FQ_B  (128 * FRS)                // 18432
#define FSB_Q 0
#define FSB_KV FQ_B                      // 18432
#define FSTG_B (2 * FTILE)               // Kf, Vf = 18432
#define FLASH_SMEM (FSB_KV + 2 * FSTG_B) // 55296

__device__ __forceinline__ void flash_load_q(uint32_t sb, int bh, int q0, int tid) {
#pragma unroll
    for (int i = 0; i < 8; i++) {
        int ch = tid + i * 128;               // 0..1023
        int r = ch >> 3, c16 = ch & 7;
        cpa16(sb + FSB_Q + r * FRS + c16 * 16,
              g_qf + ((size_t)bh * SEQ + q0 + r) * 64 + c16 * 8);
    }
}
__device__ __forceinline__ void flash_load_kv(uint32_t sb, int bh, int kbase, int stg, int tid) {
    uint32_t d0 = sb + FSB_KV + stg * FSTG_B;
#pragma unroll
    for (int i = 0; i < 8; i++) {
        int ch = tid + i * 128;               // 0..1023
        int tl = ch >> 9;                     // 0 Kf, 1 Vf
        int r = (ch >> 3) & 63, c16 = ch & 7;
        const __half* src = (tl == 0 ? g_kf : g_vf) +
            ((size_t)bh * SEQ + kbase + r) * 64 + c16 * 8;
        cpa16(d0 + tl * FTILE + r * FRS + c16 * 16, src);
    }
}

__global__ void __launch_bounds__(128, 2) flash_tc_kernel() {
    extern __shared__ char dsm[];
    uint32_t sb = smem_to_u32(dsm);
    int tid = threadIdx.x, lane = tid & 31, w = tid >> 5;
    int qt = 15 - (int)blockIdx.x;
    int bh = blockIdx.y;
    int q0 = qt * 128;
    int nkt = qt * 2 + 2;

    flash_load_q(sb, bh, q0, tid);
    flash_load_kv(sb, bh, 0, 0, tid);
    cpa_commit();

    uint32_t aQf[2][4][4];
    float o[2][8][4];
#pragma unroll
    for (int mf = 0; mf < 2; mf++)
#pragma unroll
        for (int i = 0; i < 8; i++)
#pragma unroll
            for (int j = 0; j < 4; j++) o[mf][i][j] = 0.f;
    float ls[2][2] = {{0.f, 0.f}, {0.f, 0.f}};

    uint32_t qAddr = (uint32_t)((w * 32 + (lane & 15)) * FRS + ((lane >> 4) << 4));
    uint32_t kLane = (uint32_t)((((lane >> 4) << 3) + (lane & 7)) * FRS + (((lane >> 3) & 1) << 4));
    uint32_t vLane = (uint32_t)(((lane & 7) + ((lane >> 3) & 1) * 8) * FRS + ((lane >> 4) << 4));

    for (int kt = 0; kt < nkt; kt++) {
        if (kt + 1 < nkt) {
            flash_load_kv(sb, bh, (kt + 1) * 64, (kt + 1) & 1, tid);
            cpa_commit();
            asm volatile("cp.async.wait_group 1;" ::: "memory");
        } else {
            asm volatile("cp.async.wait_group 0;" ::: "memory");
        }
        __syncthreads();

        if (kt == 0) {
#pragma unroll
            for (int mf = 0; mf < 2; mf++)
#pragma unroll
                for (int kk = 0; kk < 4; kk++)
                    ldsm4(aQf[mf][kk], sb + FSB_Q + qAddr + (uint32_t)(mf * 16 * FRS) + kk * 32);
        }

        uint32_t stg = sb + FSB_KV + (kt & 1) * FSTG_B;
        int kbase = kt * 64;

        // ---- S = Q K^T (single fp16, term-major per kk) ----
        float c[2][8][4];
#pragma unroll
        for (int mf = 0; mf < 2; mf++)
#pragma unroll
            for (int i = 0; i < 8; i++)
#pragma unroll
                for (int j = 0; j < 4; j++) c[mf][i][j] = 0.f;

#pragma unroll
        for (int kk = 0; kk < 4; kk++) {
            uint32_t bKf[4][4];
#pragma unroll
            for (int nf2 = 0; nf2 < 4; nf2++)
                ldsm4(bKf[nf2], stg + (uint32_t)(nf2 * 16 * FRS) + kLane + kk * 32);
#pragma unroll
            for (int mf = 0; mf < 2; mf++)
#pragma unroll
                for (int nf = 0; nf < 8; nf++)
                    mmah(c[mf][nf], aQf[mf][kk],
                         bKf[nf >> 1][(nf & 1) * 2], bKf[nf >> 1][(nf & 1) * 2 + 1]);
        }

        // ---- mask + exp + pack P (single fp16) ----
        bool needmask = (kbase + 63) > (q0 + w * 32);
        uint32_t aPh[2][4][4];
#pragma unroll
        for (int mf = 0; mf < 2; mf++) {
            int qrA = q0 + w * 32 + mf * 16 + (lane >> 2);
#pragma unroll
            for (int nf = 0; nf < 8; nf++) {
                if (needmask) {
                    int key0 = kbase + nf * 8 + (lane & 3) * 2;
                    if (key0 > qrA)         c[mf][nf][0] = -100000.f;
                    if (key0 + 1 > qrA)     c[mf][nf][1] = -100000.f;
                    if (key0 > qrA + 8)     c[mf][nf][2] = -100000.f;
                    if (key0 + 1 > qrA + 8) c[mf][nf][3] = -100000.f;
                }
                float p0 = ex2f(c[mf][nf][0]), p1 = ex2f(c[mf][nf][1]);
                float p2 = ex2f(c[mf][nf][2]), p3 = ex2f(c[mf][nf][3]);
                ls[mf][0] += p0 + p1;
                ls[mf][1] += p2 + p3;
                int kk = nf >> 1, sl = (nf & 1) * 2;
                aPh[mf][kk][sl]     = pack_h2(p0, p1);
                aPh[mf][kk][sl + 1] = pack_h2(p2, p3);
            }
        }

        // ---- O += P V (single fp16, term-major per kk) ----
        uint32_t vstg = stg + FTILE;
#pragma unroll
        for (int kk = 0; kk < 4; kk++) {
            uint32_t vf[4][4];
#pragma unroll
            for (int df2 = 0; df2 < 4; df2++)
                ldsm4t(vf[df2], vstg + (uint32_t)(kk * 16 * FRS) + vLane + df2 * 32);
#pragma unroll
            for (int mf = 0; mf < 2; mf++)
#pragma unroll
                for (int nf = 0; nf < 8; nf++)
                    mmah(o[mf][nf], aPh[mf][kk],
                         vf[nf >> 1][(nf & 1) * 2], vf[nf >> 1][(nf & 1) * 2 + 1]);
        }
        __syncthreads();
    }

    int b = bh >> 4, h = bh & 15;
    int colBase = h * 64 + (lane & 3) * 2;
#pragma unroll
    for (int mf = 0; mf < 2; mf++) {
        float lA = ls[mf][0], lB = ls[mf][1];
        lA += __shfl_xor_sync(0xffffffffu, lA, 1);
        lA += __shfl_xor_sync(0xffffffffu, lA, 2);
        lB += __shfl_xor_sync(0xffffffffu, lB, 1);
        lB += __shfl_xor_sync(0xffffffffu, lB, 2);
        float invA = 1.f / lA, invB = 1.f / lB;
        int rowA = b * 2048 + q0 + w * 32 + mf * 16 + (lane >> 2);
#pragma unroll
        for (int nf = 0; nf < 8; nf++) {
            int col = colBase + nf * 8;
            *(uint32_t*)(g_aof + (size_t)rowA * 1024 + col) =
                pack_h2(o[mf][nf][0] * invA, o[mf][nf][1] * invA);
            *(uint32_t*)(g_aof + (size_t)(rowA + 8) * 1024 + col) =
                pack_h2(o[mf][nf][2] * invB, o[mf][nf][3] * invB);
        }
    }
}

// ======================= launch (fork/join streams for graph capture) =======================
extern "C" void kernel_launch(void* const* d_in, const int* in_sizes, int n_in,
                              void* d_out, int out_size) {
    const float* x = (const float*)d_in[0];
    const float* Wqkv = (const float*)d_in[1];
    const float* Wout = (const float*)d_in[2];
    float* out = (float*)d_out;

    void *p_xf, *p_wqf, *p_aof, *p_wof;
    cudaGetSymbolAddress(&p_xf,  g_xf);
    cudaGetSymbolAddress(&p_wqf, g_wqf);
    cudaGetSymbolAddress(&p_aof, g_aof);
    cudaGetSymbolAddress(&p_wof, g_wof);

    cudaFuncSetAttribute(gemm_mma_kernel<0>, cudaFuncAttributeMaxDynamicSharedMemorySize, GEMM_SMEM);
    cudaFuncSetAttribute(gemm_mma_kernel<1>, cudaFuncAttributeMaxDynamicSharedMemorySize, GEMM_SMEM);
    cudaFuncSetAttribute(flash_tc_kernel, cudaFuncAttributeMaxDynamicSharedMemorySize, FLASH_SMEM);

    static cudaStream_t s2 = nullptr;
    static cudaEvent_t eStart = nullptr, eQK = nullptr, eWO = nullptr;
    if (!s2) {
        cudaStreamCreateWithFlags(&s2, cudaStreamNonBlocking);
        cudaEventCreateWithFlags(&eStart, cudaEventDisableTiming);
        cudaEventCreateWithFlags(&eQK, cudaEventDisableTiming);
        cudaEventCreateWithFlags(&eWO, cudaEventDisableTiming);
    }

    cudaEventRecord(eStart, 0);
    cudaStreamWaitEvent(s2, eStart, 0);

    rope_table_kernel<<<256, 256, 0, s2>>>();
    trans_f16_kernel<<<dim3(QKV_N / 32, D_MODEL / 32), dim3(32, 8), 0, s2>>>(
        Wqkv, (__half*)p_wqf, D_MODEL, QKV_N);
    cudaEventRecord(eQK, s2);
    trans_f16_kernel<<<dim3(D_MODEL / 32, D_MODEL / 32), dim3(32, 8), 0, s2>>>(
        Wout, (__half*)p_wof, D_MODEL, D_MODEL);
    cudaEventRecord(eWO, s2);

    conv_f16_kernel<<<4096, 256>>>(x, (__half*)p_xf, M_ROWS * D_MODEL);
    cudaStreamWaitEvent(0, eQK, 0);

    gemm_mma_kernel<0><<<dim3(QKV_N / 128, M_ROWS / 128), 128, GEMM_SMEM>>>(
        (const __half*)p_xf, (const __half*)p_wqf, nullptr);

    flash_tc_kernel<<<dim3(16, 64), 128, FLASH_SMEM>>>();

    cudaStreamWaitEvent(0, eWO, 0);
    gemm_mma_kernel<1><<<dim3(D_MODEL / 128, M_ROWS / 128), 128, GEMM_SMEM>>>(
        (const __half*)p_aof, (const __half*)p_wof, out);
}